// round 16
// baseline (speedup 1.0000x reference)
#include <cuda_runtime.h>
#include <cuda_fp16.h>
#include <cstdint>
#include <math.h>

#define N 8192
#define D 512
#define BM 128                       // CTA tile rows (A)
#define BN 256                       // CTA tile cols (B)
#define NTI (N / BM)                 // 64 row blocks
#define NTJ (N / BN)                 // 32 col blocks
#define BKC 128                      // fp8 K per chunk (128B rows)
#define NCHUNKS (D / BKC)            // 4
#define TILE_A (BM * BKC)            // 16384
#define TILE_B (BN * BKC)            // 32768
#define STAGE (TILE_A + TILE_B)      // 49152
#define SMEM_BYTES (1024 + 2 * STAGE)  // 99328 -> 2 CTAs/SM
#define QMAX 28.0f

__device__ uint8_t g_q[N * D];
__device__ float   g_scale[N];
__device__ double  g_accum;

// ---------------------------------------------------------------------------
// PTX helpers (arch-agnostic)
// ---------------------------------------------------------------------------
__device__ __forceinline__ uint32_t smem_u32(const void* p) {
    uint32_t a;
    asm("{ .reg .u64 t; cvta.to.shared.u64 t, %1; cvt.u32.u64 %0, t; }" : "=r"(a) : "l"(p));
    return a;
}
__device__ __forceinline__ void cp16(uint32_t saddr, const void* g) {
    asm volatile("cp.async.cg.shared.global [%0], [%1], 16;" :: "r"(saddr), "l"(g) : "memory");
}
__device__ __forceinline__ void cp_commit() {
    asm volatile("cp.async.commit_group;" ::: "memory");
}
template <int NN>
__device__ __forceinline__ void cp_wait() {
    asm volatile("cp.async.wait_group %0;" :: "n"(NN) : "memory");
}
__device__ __forceinline__ void ldsm_x4(uint32_t* r, uint32_t addr) {
    asm volatile("ldmatrix.sync.aligned.m8n8.x4.shared.b16 {%0,%1,%2,%3}, [%4];"
                 : "=r"(r[0]), "=r"(r[1]), "=r"(r[2]), "=r"(r[3]) : "r"(addr));
}
__device__ __forceinline__ void qmma16832_f16(uint32_t* d, const uint32_t* a,
                                              uint32_t b0, uint32_t b1) {
    asm volatile(
        "mma.sync.aligned.m16n8k32.row.col.f16.e4m3.e4m3.f16 "
        "{%0,%1}, {%2,%3,%4,%5}, {%6,%7}, {%0,%1};"
        : "+r"(d[0]), "+r"(d[1])
        : "r"(a[0]), "r"(a[1]), "r"(a[2]), "r"(a[3]), "r"(b0), "r"(b1));
}
__device__ __forceinline__ uint32_t cvt_e4m3x2(float hi, float lo) {
    uint16_t h;
    asm("cvt.rn.satfinite.e4m3x2.f32 %0, %1, %2;" : "=h"(h) : "f"(hi), "f"(lo));
    return (uint32_t)h;
}

// ---------------------------------------------------------------------------
// Kernel 1: row L2-normalize + e4m3 quantize (qmax = QMAX). One WARP per row.
// ---------------------------------------------------------------------------
__global__ __launch_bounds__(256) void quantize_kernel(const float* __restrict__ in) {
    int row  = blockIdx.x * 8 + (threadIdx.x >> 5);
    int lane = threadIdx.x & 31;
    if (blockIdx.x == 0 && threadIdx.x == 0) g_accum = 0.0;

    const float4* src = (const float4*)(in + (size_t)row * D);
    float4 v[4];
    float ss = 0.0f;
    #pragma unroll
    for (int i = 0; i < 4; i++) {
        v[i] = src[i * 32 + lane];
        ss += v[i].x * v[i].x + v[i].y * v[i].y + v[i].z * v[i].z + v[i].w * v[i].w;
    }
    #pragma unroll
    for (int o = 16; o; o >>= 1) ss += __shfl_xor_sync(0xffffffffu, ss, o);
    float inv = rsqrtf(ss);

    float amax = 0.0f;
    #pragma unroll
    for (int i = 0; i < 4; i++)
        amax = fmaxf(amax, fmaxf(fmaxf(fabsf(v[i].x), fabsf(v[i].y)),
                                 fmaxf(fabsf(v[i].z), fabsf(v[i].w))));
    amax *= inv;
    #pragma unroll
    for (int o = 16; o; o >>= 1) amax = fmaxf(amax, __shfl_xor_sync(0xffffffffu, amax, o));

    float s    = amax * (1.0f / QMAX);
    float qmul = inv * (QMAX / amax);
    if (lane == 0) g_scale[row] = s;

    uint32_t* dq = (uint32_t*)(g_q + (size_t)row * D);
    #pragma unroll
    for (int i = 0; i < 4; i++) {
        uint32_t l16 = cvt_e4m3x2(v[i].y * qmul, v[i].x * qmul);
        uint32_t h16 = cvt_e4m3x2(v[i].w * qmul, v[i].z * qmul);
        dq[i * 32 + lane] = l16 | (h16 << 16);
    }
}

// ---------------------------------------------------------------------------
// Kernel 2: 128x256 Gram tiles, QMMA e4m3 / f16 acc, 2-stage cp.async.
// 8 warps: 2 over M (64 rows) x 4 over N (64 cols); warp tile 64x64.
// Per k32 step: 8 ldsm -> 32 qmma (32 independent accumulators).
// Grid 64x32; tile (bi, bjj) live iff 2*bjj+1 >= bi; dead CTAs exit.
// ---------------------------------------------------------------------------
extern __shared__ char dynsmem[];

__global__ __launch_bounds__(256, 2) void gram_qmma_kernel() {
    int bi  = blockIdx.x & (NTI - 1);
    int bjj = blockIdx.x >> 6;
    if (2 * bjj + 1 < bi) return;                 // fully strict-lower: dead
    const bool fullUpper = (2 * bjj >= bi + 1);   // no masking needed
    const int  bias = BN * bjj - BM * bi;         // jn_global - im_global offset

    int t      = threadIdx.x;
    int wid    = t >> 5;
    int lane   = t & 31;
    int warp_m = wid & 1;
    int warp_n = wid >> 1;

    uint32_t smem0 = smem_u32(dynsmem);
    uint32_t base  = (smem0 + 1023) & ~1023u;
    uint32_t sA[2], sB[2];
    #pragma unroll
    for (int s = 0; s < 2; s++) {
        sA[s] = base + s * STAGE;
        sB[s] = sA[s] + TILE_A;
    }

    // ---- ldsm constants: addr(kk) = (stage + C) ^ (kk<<5) ----
    int r7   = lane & 7;
    int a_kh = lane >> 4;
    uint32_t swz = (uint32_t)(((a_kh ^ (r7 & 1)) << 4) | (((r7 >> 1) & 3) << 5));
    int arow = warp_m * 64 + (lane & 15);
    int brow = warp_n * 64 + (lane & 7) + (((lane >> 3) & 1) << 3);
    uint32_t cA[4], cB[4];
    #pragma unroll
    for (int mi = 0; mi < 4; mi++) cA[mi] = (uint32_t)((arow + mi * 16) * 128) + swz;
    #pragma unroll
    for (int p = 0; p < 4; p++)   cB[p]  = (uint32_t)((brow + p * 16) * 128) + swz;

    // ---- async loaders ----
    // A: 128 rows x 128B: thread t -> row t>>1, 4 chunks
    // B: 256 rows x 128B: thread t -> row t, 8 chunks
    int arow_l = t >> 1;
    const char* gpA = (const char*)(g_q + ((size_t)bi * BM + arow_l) * D);
    const char* gpB = (const char*)(g_q + ((size_t)bjj * BN + t) * D);
    uint32_t soffA[4], soffB[8];
    #pragma unroll
    for (int i = 0; i < 4; i++) {
        uint32_t c = (uint32_t)((t & 1) * 4 + i);
        soffA[i] = (uint32_t)arow_l * 128 + ((c ^ (arow_l & 7)) << 4);
    }
    #pragma unroll
    for (int i = 0; i < 8; i++)
        soffB[i] = (uint32_t)t * 128 + (((uint32_t)i ^ (t & 7)) << 4);
    int lgofsA = (t & 1) * 64;

    auto load_stage = [&](int s, int k0) {
        #pragma unroll
        for (int i = 0; i < 4; i++)
            cp16(sA[s] + soffA[i], gpA + k0 + lgofsA + i * 16);
        #pragma unroll
        for (int i = 0; i < 8; i++)
            cp16(sB[s] + soffB[i], gpB + k0 + i * 16);
        cp_commit();
    };

    uint32_t acc[4][8][2];
    #pragma unroll
    for (int mi = 0; mi < 4; mi++)
        #pragma unroll
        for (int nj = 0; nj < 8; nj++) { acc[mi][nj][0] = 0u; acc[mi][nj][1] = 0u; }

    load_stage(0, 0);
    load_stage(1, BKC);

    #pragma unroll
    for (int c = 0; c < NCHUNKS; c++) {
        if (c < NCHUNKS - 1) cp_wait<1>(); else cp_wait<0>();
        __syncthreads();

        uint32_t aBase = sA[c & 1], bBase = sB[c & 1];
        #pragma unroll
        for (int kk = 0; kk < 4; kk++) {
            uint32_t x = (uint32_t)(kk << 5);
            uint32_t Af[4][4], Bf[4][4];
            #pragma unroll
            for (int mi = 0; mi < 4; mi++) ldsm_x4(Af[mi], (aBase + cA[mi]) ^ x);
            #pragma unroll
            for (int p = 0; p < 4; p++)    ldsm_x4(Bf[p],  (bBase + cB[p])  ^ x);
            #pragma unroll
            for (int mi = 0; mi < 4; mi++)
                #pragma unroll
                for (int nj = 0; nj < 8; nj++)
                    qmma16832_f16(acc[mi][nj], Af[mi],
                                  Bf[nj >> 1][nj & 1], Bf[nj >> 1][(nj & 1) + 2]);
        }

        if (c + 2 < NCHUNKS) {
            __syncthreads();
            load_stage(c & 1, (c + 2) * BKC);
        }
    }

    // ---- epilogue: scale (s_i*s_j), relu, strict-upper mask ----
    int lrow0 = warp_m * 64 + (lane >> 2);
    int lcol0 = warp_n * 64 + (lane & 3) * 2;
    const float* scA = g_scale + bi * BM;
    const float* scB = g_scale + bjj * BN;

    float si[4][2];
    #pragma unroll
    for (int mi = 0; mi < 4; mi++)
        #pragma unroll
        for (int h = 0; h < 2; h++)
            si[mi][h] = __ldg(scA + lrow0 + mi * 16 + h * 8);

    float local = 0.0f;
    #pragma unroll
    for (int nj = 0; nj < 8; nj++) {
        int cn = lcol0 + nj * 8;
        float sj0 = __ldg(scB + cn);
        float sj1 = __ldg(scB + cn + 1);
        #pragma unroll
        for (int mi = 0; mi < 4; mi++) {
            int rm = lrow0 + mi * 16;
            #pragma unroll
            for (int r = 0; r < 2; r++) {
                int im = rm + r * 8;
                float2 f2 = __half22float2(*(__half2*)&acc[mi][nj][r]);
                float d0 = f2.x * si[mi][r] * sj0;
                float d1 = f2.y * si[mi][r] * sj1;
                bool ok0 = fullUpper || (im < cn + bias);
                bool ok1 = fullUpper || (im < cn + 1 + bias);
                if (ok0 && d0 > 0.0f) local += d0;
                if (ok1 && d1 > 0.0f) local += d1;
            }
        }
    }

    #pragma unroll
    for (int o = 16; o; o >>= 1) local += __shfl_xor_sync(0xffffffffu, local, o);
    __shared__ float red[8];
    if (lane == 0) red[wid] = local;
    __syncthreads();
    if (t == 0) {
        float s = 0.0f;
        #pragma unroll
        for (int w = 0; w < 8; w++) s += red[w];
        atomicAdd(&g_accum, (double)s);
    }
}

// ---------------------------------------------------------------------------
// Kernel 3: finalize.
// ---------------------------------------------------------------------------
__global__ void finalize_kernel(float* __restrict__ out, int out_size) {
    double v = 2.0 * g_accum / ((double)N * (double)N);
    float f = (float)v;
    out[0] = f;
    if (out_size > 1) out[1] = f;
}

extern "C" void kernel_launch(void* const* d_in, const int* in_sizes, int n_in,
                              void* d_out, int out_size) {
    const float* id = (const float*)d_in[0];
    cudaFuncSetAttribute(gram_qmma_kernel, cudaFuncAttributeMaxDynamicSharedMemorySize,
                         SMEM_BYTES);
    quantize_kernel<<<N / 8, 256>>>(id);
    gram_qmma_kernel<<<NTI * NTJ, 256, SMEM_BYTES>>>();
    finalize_kernel<<<1, 1>>>((float*)d_out, out_size);
}

// round 17
// speedup vs baseline: 1.2880x; 1.2880x over previous
#include <cuda_runtime.h>
#include <cuda_fp16.h>
#include <cstdint>
#include <math.h>

#define N 8192
#define D 512
#define BM 128
#define NT (N / BM)                 // 64
#define NPAIRS (NT * (NT + 1) / 2)  // 2080
#define BKC 128                     // fp8 K elements per chunk (128B rows)
#define NCHUNKS (D / BKC)           // 4
#define NSTAGE 3
#define TILE_BYTES (BM * BKC)       // 16384
#define SMEM_BYTES (1024 + 2 * NSTAGE * TILE_BYTES)
#define QMAX 28.0f                  // fp8 target max; keeps f16 dot_q < 65504

__device__ uint8_t  g_q[N * D];
__device__ float    g_scale[N];
__device__ double   g_accum;
__device__ unsigned g_done;         // zero-init; reset by last CTA each run

// ---------------------------------------------------------------------------
// PTX helpers (arch-agnostic)
// ---------------------------------------------------------------------------
__device__ __forceinline__ uint32_t smem_u32(const void* p) {
    uint32_t a;
    asm("{ .reg .u64 t; cvta.to.shared.u64 t, %1; cvt.u32.u64 %0, t; }" : "=r"(a) : "l"(p));
    return a;
}
__device__ __forceinline__ void cp16(uint32_t saddr, const void* g) {
    asm volatile("cp.async.cg.shared.global [%0], [%1], 16;" :: "r"(saddr), "l"(g) : "memory");
}
__device__ __forceinline__ void cp_commit() {
    asm volatile("cp.async.commit_group;" ::: "memory");
}
template <int NN>
__device__ __forceinline__ void cp_wait() {
    asm volatile("cp.async.wait_group %0;" :: "n"(NN) : "memory");
}
__device__ __forceinline__ void ldsm_x4(uint32_t* r, uint32_t addr) {
    asm volatile("ldmatrix.sync.aligned.m8n8.x4.shared.b16 {%0,%1,%2,%3}, [%4];"
                 : "=r"(r[0]), "=r"(r[1]), "=r"(r[2]), "=r"(r[3]) : "r"(addr));
}
__device__ __forceinline__ void qmma16832_f16(uint32_t* d, const uint32_t* a,
                                              uint32_t b0, uint32_t b1) {
    asm volatile(
        "mma.sync.aligned.m16n8k32.row.col.f16.e4m3.e4m3.f16 "
        "{%0,%1}, {%2,%3,%4,%5}, {%6,%7}, {%0,%1};"
        : "+r"(d[0]), "+r"(d[1])
        : "r"(a[0]), "r"(a[1]), "r"(a[2]), "r"(a[3]), "r"(b0), "r"(b1));
}
__device__ __forceinline__ uint32_t cvt_e4m3x2(float hi, float lo) {
    uint16_t h;
    asm("cvt.rn.satfinite.e4m3x2.f32 %0, %1, %2;" : "=h"(h) : "f"(hi), "f"(lo));
    return (uint32_t)h;
}

// ---------------------------------------------------------------------------
// Kernel 1: row L2-normalize + e4m3 quantize. One warp handles TWO rows
// (8 independent float4 loads in flight -> better DRAM latency hiding).
// ---------------------------------------------------------------------------
__global__ __launch_bounds__(256) void quantize_kernel(const float* __restrict__ in) {
    int warp = blockIdx.x * 8 + (threadIdx.x >> 5);
    int lane = threadIdx.x & 31;
    if (blockIdx.x == 0 && threadIdx.x == 0) g_accum = 0.0;

    #pragma unroll
    for (int rr = 0; rr < 2; rr++) {
        int row = warp * 2 + rr;
        const float4* src = (const float4*)(in + (size_t)row * D);
        float4 v[4];
        float ss = 0.0f;
        #pragma unroll
        for (int i = 0; i < 4; i++) {
            v[i] = src[i * 32 + lane];
            ss += v[i].x * v[i].x + v[i].y * v[i].y + v[i].z * v[i].z + v[i].w * v[i].w;
        }
        #pragma unroll
        for (int o = 16; o; o >>= 1) ss += __shfl_xor_sync(0xffffffffu, ss, o);
        float inv = rsqrtf(ss);

        float amax = 0.0f;
        #pragma unroll
        for (int i = 0; i < 4; i++)
            amax = fmaxf(amax, fmaxf(fmaxf(fabsf(v[i].x), fabsf(v[i].y)),
                                     fmaxf(fabsf(v[i].z), fabsf(v[i].w))));
        amax *= inv;
        #pragma unroll
        for (int o = 16; o; o >>= 1) amax = fmaxf(amax, __shfl_xor_sync(0xffffffffu, amax, o));

        float s    = amax * (1.0f / QMAX);
        float qmul = inv * (QMAX / amax);
        if (lane == 0) g_scale[row] = s;

        uint32_t* dq = (uint32_t*)(g_q + (size_t)row * D);
        #pragma unroll
        for (int i = 0; i < 4; i++) {
            uint32_t l16 = cvt_e4m3x2(v[i].y * qmul, v[i].x * qmul);
            uint32_t h16 = cvt_e4m3x2(v[i].w * qmul, v[i].z * qmul);
            dq[i * 32 + lane] = l16 | (h16 << 16);
        }
    }
}

// ---------------------------------------------------------------------------
// Kernel 2: upper-triangle 128x128 Gram tiles, QMMA e4m3 / f16 acc (R12 body).
// Last finishing CTA writes the output (folds the finalize launch).
// ---------------------------------------------------------------------------
extern __shared__ char dynsmem[];

__global__ __launch_bounds__(256, 2) void gram_qmma_kernel(float* __restrict__ out,
                                                           int out_size) {
    int b = blockIdx.x;
    int bj = (int)((sqrtf(8.0f * (float)b + 1.0f) - 1.0f) * 0.5f);
    while ((bj + 1) * (bj + 2) / 2 <= b) bj++;
    while (bj * (bj + 1) / 2 > b) bj--;
    int bi = b - bj * (bj + 1) / 2;
    const bool diag = (bi == bj);

    const uint8_t* __restrict__ gA = g_q + (size_t)bi * BM * D;
    const uint8_t* __restrict__ gB = g_q + (size_t)bj * BM * D;

    int t      = threadIdx.x;
    int wid    = t >> 5;
    int lane   = t & 31;
    int warp_m = wid & 1;
    int warp_n = wid >> 1;

    uint32_t smem0 = smem_u32(dynsmem);
    uint32_t base  = (smem0 + 1023) & ~1023u;
    uint32_t sA[NSTAGE], sB[NSTAGE];
    #pragma unroll
    for (int s = 0; s < NSTAGE; s++) {
        sA[s] = base + (2 * s)     * TILE_BYTES;
        sB[s] = base + (2 * s + 1) * TILE_BYTES;
    }

    // ---- ldsm constants: addr(kk) = (stage + C) ^ (kk<<5) ----
    int r7   = lane & 7;
    int a_kh = lane >> 4;
    uint32_t swz = (uint32_t)(((a_kh ^ (r7 & 1)) << 4) | (((r7 >> 1) & 3) << 5));
    int arow = warp_m * 64 + (lane & 15);
    int brow = warp_n * 32 + (lane & 7) + (((lane >> 3) & 1) << 3);
    uint32_t cA[4], cB[2];
    #pragma unroll
    for (int mi = 0; mi < 4; mi++) cA[mi] = (uint32_t)((arow + mi * 16) * 128) + swz;
    #pragma unroll
    for (int p = 0; p < 2; p++)   cB[p]  = (uint32_t)((brow + p * 16) * 128) + swz;

    // ---- async tile loader offsets ----
    int la_row = t >> 1;
    const char* gpA = (const char*)(gA + (size_t)la_row * D);
    const char* gpB = (const char*)(gB + (size_t)la_row * D);
    uint32_t soff[4];
    #pragma unroll
    for (int i = 0; i < 4; i++) {
        uint32_t c = (uint32_t)((t & 1) * 4 + i);
        soff[i] = (uint32_t)la_row * 128 + ((c ^ (la_row & 7)) << 4);
    }
    int lgofs = (t & 1) * 64;

    auto load_stage = [&](int s, int k0) {
        #pragma unroll
        for (int i = 0; i < 4; i++) {
            int gofs = k0 + lgofs + i * 16;
            cp16(sA[s] + soff[i], gpA + gofs);
            cp16(sB[s] + soff[i], gpB + gofs);
        }
        cp_commit();
    };

    uint32_t acc[4][4][2];
    #pragma unroll
    for (int mi = 0; mi < 4; mi++)
        #pragma unroll
        for (int nj = 0; nj < 4; nj++) { acc[mi][nj][0] = 0u; acc[mi][nj][1] = 0u; }

    load_stage(0, 0);
    load_stage(1, BKC);

    uint32_t Af[2][4][4], Bf[2][2][4];

    #pragma unroll
    for (int c = 0; c < NCHUNKS; c++) {
        if (c < NCHUNKS - 1) cp_wait<1>(); else cp_wait<0>();
        __syncthreads();

        if (c + 2 < NCHUNKS) load_stage((c + 2) % NSTAGE, (c + 2) * BKC);

        uint32_t aBase = sA[c % NSTAGE], bBase = sB[c % NSTAGE];
        uint32_t eA[4], eB[2];
        #pragma unroll
        for (int mi = 0; mi < 4; mi++) eA[mi] = aBase + cA[mi];
        #pragma unroll
        for (int p = 0; p < 2; p++)   eB[p]  = bBase + cB[p];

        #pragma unroll
        for (int mi = 0; mi < 4; mi++) ldsm_x4(Af[0][mi], eA[mi]);
        #pragma unroll
        for (int p = 0; p < 2; p++)    ldsm_x4(Bf[0][p],  eB[p]);

        #pragma unroll
        for (int kk = 0; kk < 4; kk++) {
            int cur = kk & 1;
            if (kk < 3) {
                uint32_t x = (uint32_t)((kk + 1) << 5);
                #pragma unroll
                for (int mi = 0; mi < 4; mi++) ldsm_x4(Af[cur ^ 1][mi], eA[mi] ^ x);
                #pragma unroll
                for (int p = 0; p < 2; p++)    ldsm_x4(Bf[cur ^ 1][p],  eB[p] ^ x);
            }
            #pragma unroll
            for (int mi = 0; mi < 4; mi++)
                #pragma unroll
                for (int nj = 0; nj < 4; nj++)
                    qmma16832_f16(acc[mi][nj], Af[cur][mi],
                                  Bf[cur][nj >> 1][nj & 1],
                                  Bf[cur][nj >> 1][(nj & 1) + 2]);
        }
    }

    // ---- epilogue: scale (s_i*s_j), relu, strict-upper mask ----
    int lrow0 = warp_m * 64 + (lane >> 2);
    int lcol0 = warp_n * 32 + (lane & 3) * 2;
    const float* scA = g_scale + bi * BM;
    const float* scB = g_scale + bj * BM;

    float si[4][2], sj[4][2];
    #pragma unroll
    for (int mi = 0; mi < 4; mi++)
        #pragma unroll
        for (int h = 0; h < 2; h++)
            si[mi][h] = __ldg(scA + lrow0 + mi * 16 + h * 8);
    #pragma unroll
    for (int nj = 0; nj < 4; nj++)
        #pragma unroll
        for (int bc = 0; bc < 2; bc++)
            sj[nj][bc] = __ldg(scB + lcol0 + nj * 8 + bc);

    float local = 0.0f;
    #pragma unroll
    for (int mi = 0; mi < 4; mi++)
        #pragma unroll
        for (int nj = 0; nj < 4; nj++) {
            int rm = lrow0 + mi * 16;
            int cn = lcol0 + nj * 8;
            #pragma unroll
            for (int r = 0; r < 2; r++) {
                int im = rm + r * 8;
                float2 f2 = __half22float2(*(__half2*)&acc[mi][nj][r]);
                float d0 = fmaxf(f2.x * si[mi][r] * sj[nj][0], 0.0f);
                float d1 = fmaxf(f2.y * si[mi][r] * sj[nj][1], 0.0f);
                if (diag) {
                    d0 = (im < cn)     ? d0 : 0.0f;
                    d1 = (im < cn + 1) ? d1 : 0.0f;
                }
                local += d0 + d1;
            }
        }

    #pragma unroll
    for (int o = 16; o; o >>= 1) local += __shfl_xor_sync(0xffffffffu, local, o);
    __shared__ float red[8];
    if (lane == 0) red[wid] = local;
    __syncthreads();
    if (t == 0) {
        float s = 0.0f;
        #pragma unroll
        for (int w = 0; w < 8; w++) s += red[w];
        atomicAdd(&g_accum, (double)s);
        __threadfence();
        unsigned d = atomicAdd(&g_done, 1u);
        if (d == (unsigned)(NPAIRS - 1)) {
            __threadfence();
            double v = 2.0 * g_accum / ((double)N * (double)N);
            float f = (float)v;
            out[0] = f;
            if (out_size > 1) out[1] = f;
            g_done = 0u;   // g_accum reset by quantize_kernel on next replay
            __threadfence();
        }
    }
}

extern "C" void kernel_launch(void* const* d_in, const int* in_sizes, int n_in,
                              void* d_out, int out_size) {
    const float* id = (const float*)d_in[0];
    cudaFuncSetAttribute(gram_qmma_kernel, cudaFuncAttributeMaxDynamicSharedMemorySize,
                         SMEM_BYTES);
    quantize_kernel<<<N / 16, 256>>>(id);
    gram_qmma_kernel<<<NPAIRS, 256, SMEM_BYTES>>>((float*)d_out, out_size);
}